// round 10
// baseline (speedup 1.0000x reference)
#include <cuda_runtime.h>
#include <cstdint>

#define B_DIM 32
#define S_LEN 2048
#define I_DIM 256
#define H_DIM 256

// ---------------------------------------------------------------------------
// helpers
// ---------------------------------------------------------------------------
__device__ __forceinline__ unsigned long long ffma2(unsigned long long a,
                                                    unsigned long long b,
                                                    unsigned long long c) {
    unsigned long long d;
    asm("fma.rn.f32x2 %0, %1, %2, %3;" : "=l"(d) : "l"(a), "l"(b), "l"(c));
    return d;
}
__device__ __forceinline__ unsigned long long pack2(float x, float y) {
    unsigned long long d;
    asm("mov.b64 %0, {%1, %2};" : "=l"(d) : "f"(x), "f"(y));
    return d;
}
__device__ __forceinline__ float2 unpack2(unsigned long long v) {
    float2 r;
    asm("mov.b64 {%0, %1}, %2;" : "=f"(r.x), "=f"(r.y) : "l"(v));
    return r;
}
__device__ __forceinline__ uint32_t smem_u32(const void* p) {
    uint32_t a;
    asm("{ .reg .u64 t; cvta.to.shared.u64 t, %1; cvt.u32.u64 %0, t; }"
        : "=r"(a) : "l"(p));
    return a;
}
__device__ __forceinline__ uint32_t mapa_u32(uint32_t a, uint32_t rank) {
    uint32_t d;
    asm("mapa.shared::cluster.u32 %0, %1, %2;" : "=r"(d) : "r"(a), "r"(rank));
    return d;
}
__device__ __forceinline__ void mbar_init(uint32_t mbar, uint32_t count) {
    asm volatile("mbarrier.init.shared.b64 [%0], %1;" :: "r"(mbar), "r"(count) : "memory");
}
__device__ __forceinline__ void mbar_expect_tx(uint32_t mbar, uint32_t bytes) {
    asm volatile("mbarrier.arrive.expect_tx.shared.b64 _, [%0], %1;"
                 :: "r"(mbar), "r"(bytes) : "memory");
}
__device__ __forceinline__ void mbar_wait(uint32_t mbar, uint32_t parity) {
    asm volatile(
        "{\n\t.reg .pred P;\n\t"
        "WL%=:\n\t"
        "mbarrier.try_wait.parity.acquire.cta.shared::cta.b64 P, [%0], %1, 0x989680;\n\t"
        "@!P bra WL%=;\n\t}"
        :: "r"(mbar), "r"(parity) : "memory");
}
__device__ __forceinline__ void st_async_b64(uint32_t raddr, unsigned long long v,
                                             uint32_t rmbar) {
    asm volatile(
        "st.async.shared::cluster.mbarrier::complete_tx::bytes.b64 [%0], %1, [%2];"
        :: "r"(raddr), "l"(v), "r"(rmbar) : "memory");
}
__device__ __forceinline__ float tanh_fast(float x) {
    float r;
    asm("tanh.approx.f32 %0, %1;" : "=f"(r) : "f"(x));
    return r;
}

// ---------------------------------------------------------------------------
// Kernel 1: xw[b,s,h] = x[b,s,:] . Wx_w[h,:] + Wx_b[h]  (into outputs region)
// ---------------------------------------------------------------------------
__global__ __launch_bounds__(256, 2)
void xw_gemm_kernel(const float* __restrict__ A, const float* __restrict__ W,
                    const float* __restrict__ bias, float* __restrict__ C) {
    __shared__ __align__(16) float As[16][128];
    __shared__ __align__(16) float Bs[16][128];

    const int tid = threadIdx.x;
    const int tx = tid & 15;
    const int ty = tid >> 4;
    const long bm = (long)blockIdx.x * 128;
    const long bn = (long)blockIdx.y * 128;

    const float* Ab = A + bm * I_DIM;
    const float* Wb = W + bn * I_DIM;

    unsigned long long acc[8][4];
#pragma unroll
    for (int i = 0; i < 8; i++)
#pragma unroll
        for (int j = 0; j < 4; j++) acc[i][j] = 0ull;

    for (int k0 = 0; k0 < I_DIM; k0 += 16) {
#pragma unroll
        for (int f = tid; f < 512; f += 256) {
            int row = f >> 2, kq = f & 3;
            float4 va = *(const float4*)(Ab + (long)row * I_DIM + k0 + kq * 4);
            As[kq * 4 + 0][row] = va.x; As[kq * 4 + 1][row] = va.y;
            As[kq * 4 + 2][row] = va.z; As[kq * 4 + 3][row] = va.w;
            float4 vw = *(const float4*)(Wb + (long)row * I_DIM + k0 + kq * 4);
            Bs[kq * 4 + 0][row] = vw.x; Bs[kq * 4 + 1][row] = vw.y;
            Bs[kq * 4 + 2][row] = vw.z; Bs[kq * 4 + 3][row] = vw.w;
        }
        __syncthreads();
#pragma unroll
        for (int k = 0; k < 16; k++) {
            const float4* As4 = (const float4*)&As[k][0];
            const ulonglong2* Bs2 = (const ulonglong2*)&Bs[k][0];
            float4 a0 = As4[ty * 2], a1 = As4[ty * 2 + 1];
            ulonglong2 bA = Bs2[tx * 2], bB = Bs2[tx * 2 + 1];
            unsigned long long bp[4] = {bA.x, bA.y, bB.x, bB.y};
            float av[8] = {a0.x, a0.y, a0.z, a0.w, a1.x, a1.y, a1.z, a1.w};
#pragma unroll
            for (int i = 0; i < 8; i++) {
                unsigned long long ap = pack2(av[i], av[i]);
#pragma unroll
                for (int j = 0; j < 4; j++) acc[i][j] = ffma2(ap, bp[j], acc[i][j]);
            }
        }
        __syncthreads();
    }

    float bv[8];
#pragma unroll
    for (int j = 0; j < 8; j++) bv[j] = bias[bn + tx * 8 + j];
#pragma unroll
    for (int i = 0; i < 8; i++) {
        long m = bm + ty * 8 + i;
        float* Crow = C + m * (long)H_DIM + bn + tx * 8;
        float2 c0 = unpack2(acc[i][0]), c1 = unpack2(acc[i][1]);
        float2 c2 = unpack2(acc[i][2]), c3 = unpack2(acc[i][3]);
        *(float4*)(Crow)     = make_float4(c0.x + bv[0], c0.y + bv[1], c1.x + bv[2], c1.y + bv[3]);
        *(float4*)(Crow + 4) = make_float4(c2.x + bv[4], c2.y + bv[5], c3.x + bv[6], c3.y + bv[7]);
    }
}

// ---------------------------------------------------------------------------
// Kernel 2: recurrence, TWO batch rows per cluster, partial-sum exchange.
// Same weights serve both rows (Wh shared across batch). Interleaving rows A
// and B hides each row's DSMEM transit behind the other row's compute:
//   per step, per row: wait(partials shipped one full row-phase ago) -> tanh
//   -> STS h -> bar -> compute+ship partials for NEXT step -> local partial.
// ---------------------------------------------------------------------------
__global__ __launch_bounds__(256, 1) __cluster_dims__(2, 1, 1)
void srnn_recur_kernel(const float* __restrict__ Wh, float* __restrict__ out) {
    __shared__ __align__(16) float hS[2][2][128];    // [row][buf][jl] my h half
    __shared__ __align__(16) float pbuf[2][2][128];  // incoming peer partials
    __shared__ __align__(8) unsigned long long mbar[2][2];

    const int rank = blockIdx.x;
    const int cid  = blockIdx.y;          // 0..15
    const int t    = threadIdx.x;
    const int jl   = t >> 1;              // 0..127
    const int kc   = t & 1;               // 0..1 (64 k each within my half)
    const int jg   = rank * 128 + jl;     // my output column
    const int jp   = (rank ^ 1) * 128 + jl;  // peer output I help with

    // --- preload weights (shared by both rows): peer rows + my rows, my k-half
    unsigned long long wPA[16], wPB[16], wLA[16], wLB[16];
    {
        const float* wp = Wh + (long)jp * H_DIM + (rank * 128 + kc * 64);
        const float* wl = Wh + (long)jg * H_DIM + (rank * 128 + kc * 64);
#pragma unroll
        for (int u = 0; u < 16; u++) {
            ulonglong2 a = *(const ulonglong2*)(wp + u * 4);
            wPA[u] = a.x; wPB[u] = a.y;
            ulonglong2 b = *(const ulonglong2*)(wl + u * 4);
            wLA[u] = b.x; wLB[u] = b.y;
        }
    }

    uint32_t mb[2][2];
#pragma unroll
    for (int r = 0; r < 2; r++)
#pragma unroll
        for (int b = 0; b < 2; b++) mb[r][b] = smem_u32(&mbar[r][b]);

    if (t == 0) {
#pragma unroll
        for (int r = 0; r < 2; r++)
#pragma unroll
            for (int b = 0; b < 2; b++) {
                mbar_init(mb[r][b], 1);
                mbar_expect_tx(mb[r][b], 512);
            }
    }
    if (t < 128) { hS[0][0][t] = 0.0f; hS[1][0][t] = 0.0f; }
    __syncthreads();
    asm volatile("barrier.cluster.arrive.aligned;" ::: "memory");
    asm volatile("barrier.cluster.wait.aligned;" ::: "memory");

    uint32_t prB[2][2], pmb[2][2];
#pragma unroll
    for (int r = 0; r < 2; r++)
#pragma unroll
        for (int b = 0; b < 2; b++) {
            prB[r][b] = mapa_u32(smem_u32(&pbuf[r][b][0]), rank ^ 1);
            pmb[r][b] = mapa_u32(mb[r][b], rank ^ 1);
        }

    // kc==0 lanes with even jl ship the pair {P_jl, P_jl+1} (64 x 8B = 512B)
    const bool shipper = (kc == 0) && ((jl & 1) == 0);
    const uint32_t shipoff = (uint32_t)jl * 4u;

    // prologue: step-0 partials are zero (h0 = 0) -> ship zeros into buf 0
    if (shipper) {
        st_async_b64(prB[0][0] + shipoff, 0ull, pmb[0][0]);
        st_async_b64(prB[1][0] + shipoff, 0ull, pmb[1][0]);
    }

    float* xwp0 = out + (long)(cid * 2)     * S_LEN * H_DIM + jg;
    float* xwp1 = out + (long)(cid * 2 + 1) * S_LEN * H_DIM + jg;
    float xw_next[2] = { xwp0[0], xwp1[0] };
    float L[2] = { 0.0f, 0.0f };

    for (int step = 0; step < S_LEN; step++) {
        const int b = step & 1;
        const uint32_t par = (step >> 1) & 1;

#pragma unroll
        for (int r = 0; r < 2; r++) {
            float* xwp = r ? xwp1 : xwp0;

            // ---- finish this row's step: partials were shipped one full
            //      row-phase ago (transit hidden behind the other row)
            mbar_wait(mb[r][b], par);
            if (t == 3) mbar_expect_tx(mb[r][b], 512);   // re-arm for step+2

            float v = tanh_fast(L[r] + pbuf[r][b][jl] + xw_next[r]);
            if (step + 1 < S_LEN)
                xw_next[r] = xwp[(long)(step + 1) * H_DIM];

            if (kc == 0) {
                hS[r][b ^ 1][jl] = v;                 // h(step+1), my half
            } else {
                xwp[(long)step * H_DIM] = v;          // in-place output
                if (step == S_LEN - 1)
                    out[(long)B_DIM * S_LEN * H_DIM +
                        (long)(cid * 2 + r) * H_DIM + jg] = v;
            }
            __syncthreads();   // h(step+1) visible CTA-wide

            const ulonglong2* h2 = (const ulonglong2*)&hS[r][b ^ 1][kc * 64];

            // ---- PEER partials from h(step+1): ship ASAP ----
            unsigned long long p0 = 0ull, p1 = 0ull, p2 = 0ull, p3 = 0ull;
#pragma unroll
            for (int u = 0; u < 16; u += 2) {
                ulonglong2 hv0 = h2[u], hv1 = h2[u + 1];
                p0 = ffma2(hv0.x, wPA[u], p0);
                p1 = ffma2(hv0.y, wPB[u], p1);
                p2 = ffma2(hv1.x, wPA[u + 1], p2);
                p3 = ffma2(hv1.y, wPB[u + 1], p3);
            }
            float2 g0 = unpack2(p0), g1 = unpack2(p1);
            float2 g2 = unpack2(p2), g3 = unpack2(p3);
            float P = ((g0.x + g0.y) + (g1.x + g1.y)) +
                      ((g2.x + g2.y) + (g3.x + g3.y));
            P += __shfl_xor_sync(0xffffffffu, P, 1);
            float Phi = __shfl_down_sync(0xffffffffu, P, 2);

            if (shipper && step + 1 < S_LEN)
                st_async_b64(prB[r][b ^ 1] + shipoff, pack2(P, Phi),
                             pmb[r][b ^ 1]);

            // ---- LOCAL partial for the next step ----
            unsigned long long a0 = 0ull, a1 = 0ull, a2 = 0ull, a3 = 0ull;
#pragma unroll
            for (int u = 0; u < 16; u += 2) {
                ulonglong2 hv0 = h2[u], hv1 = h2[u + 1];
                a0 = ffma2(hv0.x, wLA[u], a0);
                a1 = ffma2(hv0.y, wLB[u], a1);
                a2 = ffma2(hv1.x, wLA[u + 1], a2);
                a3 = ffma2(hv1.y, wLB[u + 1], a3);
            }
            float2 f0 = unpack2(a0), f1 = unpack2(a1);
            float2 f2 = unpack2(a2), f3 = unpack2(a3);
            float Ln = ((f0.x + f0.y) + (f1.x + f1.y)) +
                       ((f2.x + f2.y) + (f3.x + f3.y));
            Ln += __shfl_xor_sync(0xffffffffu, Ln, 1);
            L[r] = Ln;
        }
    }

    asm volatile("barrier.cluster.arrive.aligned;" ::: "memory");
    asm volatile("barrier.cluster.wait.aligned;" ::: "memory");
}

// ---------------------------------------------------------------------------
// Launch
// ---------------------------------------------------------------------------
extern "C" void kernel_launch(void* const* d_in, const int* in_sizes, int n_in,
                              void* d_out, int out_size) {
    const float* x    = (const float*)d_in[0];  // [B,S,I]
    const float* Wx_w = (const float*)d_in[1];  // [H,I]
    const float* Wx_b = (const float*)d_in[2];  // [H]
    const float* Wh_w = (const float*)d_in[3];  // [H,H]
    float* out = (float*)d_out;                 // [B,S,H] ++ [B,H]

    dim3 g1((B_DIM * S_LEN) / 128, H_DIM / 128);
    xw_gemm_kernel<<<g1, 256>>>(x, Wx_w, Wx_b, out);

    dim3 g2(2, B_DIM / 2);                      // 16 clusters x 2 CTAs
    srnn_recur_kernel<<<g2, 256>>>(Wh_w, out);
}

// round 11
// speedup vs baseline: 2.0201x; 2.0201x over previous
#include <cuda_runtime.h>
#include <cstdint>

#define B_DIM 32
#define S_LEN 2048
#define I_DIM 256
#define H_DIM 256
#define CHUNK 128
#define N_CHUNKS (S_LEN / CHUNK)          // 16
#define REC_Y 32                          // recurrence blocks: y in [0,32)
#define GEMM_MT (B_DIM * N_CHUNKS)        // 512 m-tiles

// chunk-ready flags: flag[row][chunk] counts finished N-tiles (2 = ready)
__device__ int g_flags[B_DIM][N_CHUNKS];

// ---------------------------------------------------------------------------
// helpers
// ---------------------------------------------------------------------------
__device__ __forceinline__ unsigned long long ffma2(unsigned long long a,
                                                    unsigned long long b,
                                                    unsigned long long c) {
    unsigned long long d;
    asm("fma.rn.f32x2 %0, %1, %2, %3;" : "=l"(d) : "l"(a), "l"(b), "l"(c));
    return d;
}
__device__ __forceinline__ unsigned long long pack2(float x, float y) {
    unsigned long long d;
    asm("mov.b64 %0, {%1, %2};" : "=l"(d) : "f"(x), "f"(y));
    return d;
}
__device__ __forceinline__ float2 unpack2(unsigned long long v) {
    float2 r;
    asm("mov.b64 {%0, %1}, %2;" : "=f"(r.x), "=f"(r.y) : "l"(v));
    return r;
}
__device__ __forceinline__ uint32_t smem_u32(const void* p) {
    uint32_t a;
    asm("{ .reg .u64 t; cvta.to.shared.u64 t, %1; cvt.u32.u64 %0, t; }"
        : "=r"(a) : "l"(p));
    return a;
}
__device__ __forceinline__ uint32_t mapa_u32(uint32_t a, uint32_t rank) {
    uint32_t d;
    asm("mapa.shared::cluster.u32 %0, %1, %2;" : "=r"(d) : "r"(a), "r"(rank));
    return d;
}
__device__ __forceinline__ void mbar_init(uint32_t mbar, uint32_t count) {
    asm volatile("mbarrier.init.shared.b64 [%0], %1;" :: "r"(mbar), "r"(count) : "memory");
}
__device__ __forceinline__ void mbar_expect_tx(uint32_t mbar, uint32_t bytes) {
    asm volatile("mbarrier.arrive.expect_tx.shared.b64 _, [%0], %1;"
                 :: "r"(mbar), "r"(bytes) : "memory");
}
__device__ __forceinline__ void mbar_wait(uint32_t mbar, uint32_t parity) {
    asm volatile(
        "{\n\t.reg .pred P;\n\t"
        "WL%=:\n\t"
        "mbarrier.try_wait.parity.acquire.cta.shared::cta.b64 P, [%0], %1, 0x989680;\n\t"
        "@!P bra WL%=;\n\t}"
        :: "r"(mbar), "r"(parity) : "memory");
}
__device__ __forceinline__ void st_async_b64(uint32_t raddr, unsigned long long v,
                                             uint32_t rmbar) {
    asm volatile(
        "st.async.shared::cluster.mbarrier::complete_tx::bytes.b64 [%0], %1, [%2];"
        :: "r"(raddr), "l"(v), "r"(rmbar) : "memory");
}
__device__ __forceinline__ float tanh_fast(float x) {
    float r;
    asm("tanh.approx.f32 %0, %1;" : "=f"(r) : "f"(x));
    return r;
}

// ---------------------------------------------------------------------------
// flag reset (graph replays reuse device globals -> reset every launch)
// ---------------------------------------------------------------------------
__global__ void flag_init_kernel() {
    int i = threadIdx.x;
    if (i < B_DIM * N_CHUNKS) ((int*)g_flags)[i] = 0;
}

// ---------------------------------------------------------------------------
// Fused kernel: grid (2, REC_Y + GEMM_MT), 256 threads, cluster (2,1,1).
//   y <  REC_Y : recurrence cluster for batch row y (rank = x)  [R9 design]
//   y >= REC_Y : GEMM block for m-tile (y-REC_Y) [chunk-major], n-tile x
// ---------------------------------------------------------------------------
__global__ __launch_bounds__(256, 1) __cluster_dims__(2, 1, 1)
void srnn_fused_kernel(const float* __restrict__ x,
                       const float* __restrict__ Wx_w,
                       const float* __restrict__ Wx_b,
                       const float* __restrict__ Wh,
                       float* __restrict__ out) {
    __shared__ __align__(16) unsigned char arena[16384];
    const int t = threadIdx.x;

    if (blockIdx.y >= REC_Y) {
        // =================== GEMM: xw tile into outputs region ===========
        float (*As)[128] = (float(*)[128])(arena);
        float (*Bs)[128] = (float(*)[128])(arena + 8192);

        const int y2      = blockIdx.y - REC_Y;
        const int s_chunk = y2 >> 5;           // 0..15  (chunk-major order)
        const int b       = y2 & 31;           // 0..31
        const long bm = (long)b * S_LEN + (long)s_chunk * CHUNK;
        const long bn = (long)blockIdx.x * 128;

        const int tx = t & 15;
        const int ty = t >> 4;
        const float* Ab = x + bm * I_DIM;
        const float* Wb = Wx_w + bn * I_DIM;

        unsigned long long acc[8][4];
#pragma unroll
        for (int i = 0; i < 8; i++)
#pragma unroll
            for (int j = 0; j < 4; j++) acc[i][j] = 0ull;

        for (int k0 = 0; k0 < I_DIM; k0 += 16) {
#pragma unroll
            for (int f = t; f < 512; f += 256) {
                int row = f >> 2, kq = f & 3;
                float4 va = *(const float4*)(Ab + (long)row * I_DIM + k0 + kq * 4);
                As[kq * 4 + 0][row] = va.x; As[kq * 4 + 1][row] = va.y;
                As[kq * 4 + 2][row] = va.z; As[kq * 4 + 3][row] = va.w;
                float4 vw = *(const float4*)(Wb + (long)row * I_DIM + k0 + kq * 4);
                Bs[kq * 4 + 0][row] = vw.x; Bs[kq * 4 + 1][row] = vw.y;
                Bs[kq * 4 + 2][row] = vw.z; Bs[kq * 4 + 3][row] = vw.w;
            }
            __syncthreads();
#pragma unroll
            for (int k = 0; k < 16; k++) {
                const float4* As4 = (const float4*)&As[k][0];
                const ulonglong2* Bs2 = (const ulonglong2*)&Bs[k][0];
                float4 a0 = As4[ty * 2], a1 = As4[ty * 2 + 1];
                ulonglong2 bA = Bs2[tx * 2], bB = Bs2[tx * 2 + 1];
                unsigned long long bp[4] = {bA.x, bA.y, bB.x, bB.y};
                float av[8] = {a0.x, a0.y, a0.z, a0.w, a1.x, a1.y, a1.z, a1.w};
#pragma unroll
                for (int i = 0; i < 8; i++) {
                    unsigned long long ap = pack2(av[i], av[i]);
#pragma unroll
                    for (int j = 0; j < 4; j++) acc[i][j] = ffma2(ap, bp[j], acc[i][j]);
                }
            }
            __syncthreads();
        }

        float bv[8];
#pragma unroll
        for (int j = 0; j < 8; j++) bv[j] = Wx_b[bn + tx * 8 + j];
#pragma unroll
        for (int i = 0; i < 8; i++) {
            long m = bm + ty * 8 + i;
            float* Crow = out + m * (long)H_DIM + bn + tx * 8;
            float2 c0 = unpack2(acc[i][0]), c1 = unpack2(acc[i][1]);
            float2 c2 = unpack2(acc[i][2]), c3 = unpack2(acc[i][3]);
            *(float4*)(Crow)     = make_float4(c0.x + bv[0], c0.y + bv[1], c1.x + bv[2], c1.y + bv[3]);
            *(float4*)(Crow + 4) = make_float4(c2.x + bv[4], c2.y + bv[5], c3.x + bv[6], c3.y + bv[7]);
        }

        __threadfence();
        __syncthreads();
        if (t == 0) atomicAdd(&g_flags[b][s_chunk], 1);
        return;
    }

    // ====================== recurrence (R9, unchanged) ====================
    float (*hS)[128]   = (float(*)[128])(arena);          // [buf][jl] my h half
    float (*pbuf)[128] = (float(*)[128])(arena + 1024);   // incoming partials
    unsigned long long* mbarp = (unsigned long long*)(arena + 2048);

    const int rank = blockIdx.x;
    const int row  = blockIdx.y;
    const int jl   = t >> 1;
    const int kc   = t & 1;
    const int jg   = rank * 128 + jl;
    const int jp   = (rank ^ 1) * 128 + jl;

    unsigned long long wPA[16], wPB[16], wLA[16], wLB[16];
    {
        const float* wp = Wh + (long)jp * H_DIM + (rank * 128 + kc * 64);
        const float* wl = Wh + (long)jg * H_DIM + (rank * 128 + kc * 64);
#pragma unroll
        for (int u = 0; u < 16; u++) {
            ulonglong2 a = *(const ulonglong2*)(wp + u * 4);
            wPA[u] = a.x; wPB[u] = a.y;
            ulonglong2 b2 = *(const ulonglong2*)(wl + u * 4);
            wLA[u] = b2.x; wLB[u] = b2.y;
        }
    }

    const uint32_t mb0 = smem_u32(&mbarp[0]);
    const uint32_t mb1 = smem_u32(&mbarp[1]);

    if (t == 0) {
        mbar_init(mb0, 1);
        mbar_init(mb1, 1);
        mbar_expect_tx(mb0, 512);
        mbar_expect_tx(mb1, 512);
    }
    if (t < 128) hS[0][t] = 0.0f;
    __syncthreads();
    asm volatile("barrier.cluster.arrive.aligned;" ::: "memory");
    asm volatile("barrier.cluster.wait.aligned;" ::: "memory");

    const uint32_t prB0 = mapa_u32(smem_u32(&pbuf[0][0]), rank ^ 1);
    const uint32_t prB1 = mapa_u32(smem_u32(&pbuf[1][0]), rank ^ 1);
    const uint32_t pmb0 = mapa_u32(mb0, rank ^ 1);
    const uint32_t pmb1 = mapa_u32(mb1, rank ^ 1);

    const bool shipper = (kc == 0) && ((jl & 1) == 0);
    const uint32_t shipoff = (uint32_t)jl * 4u;

    // wait for xw chunk 0 (t0 spins, block follows)
    {
        if (t == 0) {
            volatile int* f = &g_flags[row][0];
            while (*f < 2) __nanosleep(512);
        }
        __syncthreads();
        __threadfence();
    }

    float* xwp = out + (long)row * S_LEN * H_DIM + jg;
    float xw_next = xwp[0];

    for (int step = 0; step < S_LEN; step++) {
        const int b = step & 1;
        float xw_cur = xw_next;
        if (step + 1 < S_LEN) {
            if (((step + 1) & (CHUNK - 1)) == 0) {      // entering a new chunk
                if (t == 0) {
                    volatile int* f = &g_flags[row][(step + 1) >> 7];
                    while (*f < 2) __nanosleep(512);
                }
                __syncthreads();
                __threadfence();
            }
            xw_next = xwp[(long)(step + 1) * H_DIM];
        }

        const ulonglong2* h2 = (const ulonglong2*)&hS[b][kc * 64];

        // ---- PEER partial: ship ASAP ----
        unsigned long long p0 = 0ull, p1 = 0ull, p2 = 0ull, p3 = 0ull;
#pragma unroll
        for (int u = 0; u < 16; u += 2) {
            ulonglong2 hv0 = h2[u], hv1 = h2[u + 1];
            p0 = ffma2(hv0.x, wPA[u], p0);
            p1 = ffma2(hv0.y, wPB[u], p1);
            p2 = ffma2(hv1.x, wPA[u + 1], p2);
            p3 = ffma2(hv1.y, wPB[u + 1], p3);
        }
        float2 g0 = unpack2(p0), g1 = unpack2(p1);
        float2 g2 = unpack2(p2), g3 = unpack2(p3);
        float P = ((g0.x + g0.y) + (g1.x + g1.y)) +
                  ((g2.x + g2.y) + (g3.x + g3.y));
        P += __shfl_xor_sync(0xffffffffu, P, 1);
        float Phi = __shfl_down_sync(0xffffffffu, P, 2);

        if (shipper)
            st_async_b64((b ? prB1 : prB0) + shipoff, pack2(P, Phi),
                         b ? pmb1 : pmb0);

        // ---- LOCAL partial (overlaps the transit) ----
        unsigned long long a0 = 0ull, a1 = 0ull, a2 = 0ull, a3 = 0ull;
#pragma unroll
        for (int u = 0; u < 16; u += 2) {
            ulonglong2 hv0 = h2[u], hv1 = h2[u + 1];
            a0 = ffma2(hv0.x, wLA[u], a0);
            a1 = ffma2(hv0.y, wLB[u], a1);
            a2 = ffma2(hv1.x, wLA[u + 1], a2);
            a3 = ffma2(hv1.y, wLB[u + 1], a3);
        }
        float2 f0 = unpack2(a0), f1 = unpack2(a1);
        float2 f2 = unpack2(a2), f3 = unpack2(a3);
        float L = ((f0.x + f0.y) + (f1.x + f1.y)) +
                  ((f2.x + f2.y) + (f3.x + f3.y));
        L += __shfl_xor_sync(0xffffffffu, L, 1);

        // ---- wait for peer's partials, finish the step ----
        mbar_wait(b ? mb1 : mb0, (step >> 1) & 1);
        if (t == 3) mbar_expect_tx(b ? mb1 : mb0, 512);

        float v = tanh_fast(L + pbuf[b][jl] + xw_cur);

        if (kc == 0) {
            hS[b ^ 1][jl] = v;
        } else {
            xwp[(long)step * H_DIM] = v;
            if (step == S_LEN - 1)
                out[(long)B_DIM * S_LEN * H_DIM + (long)row * H_DIM + jg] = v;
        }

        __syncthreads();
    }

    asm volatile("barrier.cluster.arrive.aligned;" ::: "memory");
    asm volatile("barrier.cluster.wait.aligned;" ::: "memory");
}

// ---------------------------------------------------------------------------
// Launch
// ---------------------------------------------------------------------------
extern "C" void kernel_launch(void* const* d_in, const int* in_sizes, int n_in,
                              void* d_out, int out_size) {
    const float* x    = (const float*)d_in[0];  // [B,S,I]
    const float* Wx_w = (const float*)d_in[1];  // [H,I]
    const float* Wx_b = (const float*)d_in[2];  // [H]
    const float* Wh_w = (const float*)d_in[3];  // [H,H]
    float* out = (float*)d_out;                 // [B,S,H] ++ [B,H]

    flag_init_kernel<<<1, 512>>>();

    dim3 g(2, REC_Y + GEMM_MT);                 // (2, 544)
    srnn_fused_kernel<<<g, 256>>>(x, Wx_w, Wx_b, Wh_w, out);
}

// round 12
// speedup vs baseline: 2.8120x; 1.3920x over previous
#include <cuda_runtime.h>
#include <cstdint>

#define B_DIM 32
#define S_LEN 2048
#define I_DIM 256
#define H_DIM 256
#define CHUNK 128
#define N_CHUNKS (S_LEN / CHUNK)          // 16
#define REC_Y 32                          // recurrence blocks: y in [0,32)
#define GEMM_MT (B_DIM * N_CHUNKS)        // 512 m-tiles

// chunk-ready flags: flag[row][chunk] counts finished N-tiles (2 = ready)
__device__ int g_flags[B_DIM][N_CHUNKS];

// ---------------------------------------------------------------------------
// helpers
// ---------------------------------------------------------------------------
__device__ __forceinline__ unsigned long long ffma2(unsigned long long a,
                                                    unsigned long long b,
                                                    unsigned long long c) {
    unsigned long long d;
    asm("fma.rn.f32x2 %0, %1, %2, %3;" : "=l"(d) : "l"(a), "l"(b), "l"(c));
    return d;
}
__device__ __forceinline__ unsigned long long pack2(float x, float y) {
    unsigned long long d;
    asm("mov.b64 %0, {%1, %2};" : "=l"(d) : "f"(x), "f"(y));
    return d;
}
__device__ __forceinline__ float2 unpack2(unsigned long long v) {
    float2 r;
    asm("mov.b64 {%0, %1}, %2;" : "=f"(r.x), "=f"(r.y) : "l"(v));
    return r;
}
__device__ __forceinline__ uint32_t smem_u32(const void* p) {
    uint32_t a;
    asm("{ .reg .u64 t; cvta.to.shared.u64 t, %1; cvt.u32.u64 %0, t; }"
        : "=r"(a) : "l"(p));
    return a;
}
__device__ __forceinline__ uint32_t mapa_u32(uint32_t a, uint32_t rank) {
    uint32_t d;
    asm("mapa.shared::cluster.u32 %0, %1, %2;" : "=r"(d) : "r"(a), "r"(rank));
    return d;
}
__device__ __forceinline__ void mbar_init(uint32_t mbar, uint32_t count) {
    asm volatile("mbarrier.init.shared.b64 [%0], %1;" :: "r"(mbar), "r"(count) : "memory");
}
__device__ __forceinline__ void mbar_expect_tx(uint32_t mbar, uint32_t bytes) {
    asm volatile("mbarrier.arrive.expect_tx.shared.b64 _, [%0], %1;"
                 :: "r"(mbar), "r"(bytes) : "memory");
}
__device__ __forceinline__ void mbar_wait(uint32_t mbar, uint32_t parity) {
    asm volatile(
        "{\n\t.reg .pred P;\n\t"
        "WL%=:\n\t"
        "mbarrier.try_wait.parity.acquire.cta.shared::cta.b64 P, [%0], %1, 0x989680;\n\t"
        "@!P bra WL%=;\n\t}"
        :: "r"(mbar), "r"(parity) : "memory");
}
__device__ __forceinline__ void st_async_f32(uint32_t raddr, float v, uint32_t rmbar) {
    asm volatile(
        "st.async.shared::cluster.mbarrier::complete_tx::bytes.f32 [%0], %1, [%2];"
        :: "r"(raddr), "f"(v), "r"(rmbar) : "memory");
}
__device__ __forceinline__ float tanh_fast(float x) {
    float r;
    asm("tanh.approx.f32 %0, %1;" : "=f"(r) : "f"(x));
    return r;
}

// ---------------------------------------------------------------------------
// flag reset (graph replays reuse device globals -> reset every launch)
// ---------------------------------------------------------------------------
__global__ void flag_init_kernel() {
    int i = threadIdx.x;
    if (i < B_DIM * N_CHUNKS) ((int*)g_flags)[i] = 0;
}

// ---------------------------------------------------------------------------
// Fused kernel: grid (2, REC_Y + GEMM_MT), 256 threads, cluster (2,1,1).
//   y <  REC_Y : recurrence cluster for batch row y (rank = x)
//   y >= REC_Y : GEMM block for m-tile (y-REC_Y) [chunk-major], n-tile x
// ---------------------------------------------------------------------------
__global__ __launch_bounds__(256, 1) __cluster_dims__(2, 1, 1)
void srnn_fused_kernel(const float* __restrict__ x,
                       const float* __restrict__ Wx_w,
                       const float* __restrict__ Wx_b,
                       const float* __restrict__ Wh,
                       float* __restrict__ out) {
    __shared__ __align__(16) unsigned char arena[16384];
    const int t = threadIdx.x;

    if (blockIdx.y >= REC_Y) {
        // =================== GEMM: xw tile into outputs region ===========
        float (*As)[128] = (float(*)[128])(arena);
        float (*Bs)[128] = (float(*)[128])(arena + 8192);

        const int y2      = blockIdx.y - REC_Y;
        const int s_chunk = y2 >> 5;           // 0..15  (chunk-major order)
        const int b       = y2 & 31;           // 0..31
        const long bm = (long)b * S_LEN + (long)s_chunk * CHUNK;
        const long bn = (long)blockIdx.x * 128;

        const int tx = t & 15;
        const int ty = t >> 4;
        const float* Ab = x + bm * I_DIM;
        const float* Wb = Wx_w + bn * I_DIM;

        unsigned long long acc[8][4];
#pragma unroll
        for (int i = 0; i < 8; i++)
#pragma unroll
            for (int j = 0; j < 4; j++) acc[i][j] = 0ull;

        for (int k0 = 0; k0 < I_DIM; k0 += 16) {
#pragma unroll
            for (int f = t; f < 512; f += 256) {
                int row = f >> 2, kq = f & 3;
                float4 va = *(const float4*)(Ab + (long)row * I_DIM + k0 + kq * 4);
                As[kq * 4 + 0][row] = va.x; As[kq * 4 + 1][row] = va.y;
                As[kq * 4 + 2][row] = va.z; As[kq * 4 + 3][row] = va.w;
                float4 vw = *(const float4*)(Wb + (long)row * I_DIM + k0 + kq * 4);
                Bs[kq * 4 + 0][row] = vw.x; Bs[kq * 4 + 1][row] = vw.y;
                Bs[kq * 4 + 2][row] = vw.z; Bs[kq * 4 + 3][row] = vw.w;
            }
            __syncthreads();
#pragma unroll
            for (int k = 0; k < 16; k++) {
                const float4* As4 = (const float4*)&As[k][0];
                const ulonglong2* Bs2 = (const ulonglong2*)&Bs[k][0];
                float4 a0 = As4[ty * 2], a1 = As4[ty * 2 + 1];
                ulonglong2 bA = Bs2[tx * 2], bB = Bs2[tx * 2 + 1];
                unsigned long long bp[4] = {bA.x, bA.y, bB.x, bB.y};
                float av[8] = {a0.x, a0.y, a0.z, a0.w, a1.x, a1.y, a1.z, a1.w};
#pragma unroll
                for (int i = 0; i < 8; i++) {
                    unsigned long long ap = pack2(av[i], av[i]);
#pragma unroll
                    for (int j = 0; j < 4; j++) acc[i][j] = ffma2(ap, bp[j], acc[i][j]);
                }
            }
            __syncthreads();
        }

        float bv[8];
#pragma unroll
        for (int j = 0; j < 8; j++) bv[j] = Wx_b[bn + tx * 8 + j];
#pragma unroll
        for (int i = 0; i < 8; i++) {
            long m = bm + ty * 8 + i;
            float* Crow = out + m * (long)H_DIM + bn + tx * 8;
            float2 c0 = unpack2(acc[i][0]), c1 = unpack2(acc[i][1]);
            float2 c2 = unpack2(acc[i][2]), c3 = unpack2(acc[i][3]);
            *(float4*)(Crow)     = make_float4(c0.x + bv[0], c0.y + bv[1], c1.x + bv[2], c1.y + bv[3]);
            *(float4*)(Crow + 4) = make_float4(c2.x + bv[4], c2.y + bv[5], c3.x + bv[6], c3.y + bv[7]);
        }

        __threadfence();
        __syncthreads();
        if (t == 0) atomicAdd(&g_flags[b][s_chunk], 1);
        return;
    }

    // ====================== recurrence ====================================
    // h stored INTERLEAVED: pos(k) = ((k&63)>>2)*8 + ((k>>6)<<2) + (k&3)
    // so kc0/kc1 lanes' 16B reads sit 16B apart -> one L1 wavefront per LDS.
    float (*hS)[128]   = (float(*)[128])(arena);          // [buf][pos] my h half
    float (*pbuf)[128] = (float(*)[128])(arena + 1024);   // incoming partials
    unsigned long long* mbarp = (unsigned long long*)(arena + 2048);

    const int rank = blockIdx.x;
    const int row  = blockIdx.y;
    const int jl   = t >> 1;
    const int kc   = t & 1;
    const int jg   = rank * 128 + jl;
    const int jp   = (rank ^ 1) * 128 + jl;
    // interleaved write position for my h value (k = jl)
    const int hpos = ((jl & 63) >> 2) * 8 + ((jl >> 6) << 2) + (jl & 3);

    unsigned long long wPA[16], wPB[16], wLA[16], wLB[16];
    {
        const float* wp = Wh + (long)jp * H_DIM + (rank * 128 + kc * 64);
        const float* wl = Wh + (long)jg * H_DIM + (rank * 128 + kc * 64);
#pragma unroll
        for (int u = 0; u < 16; u++) {
            ulonglong2 a = *(const ulonglong2*)(wp + u * 4);
            wPA[u] = a.x; wPB[u] = a.y;
            ulonglong2 b2 = *(const ulonglong2*)(wl + u * 4);
            wLA[u] = b2.x; wLB[u] = b2.y;
        }
    }

    const uint32_t mb0 = smem_u32(&mbarp[0]);
    const uint32_t mb1 = smem_u32(&mbarp[1]);

    if (t == 0) {
        mbar_init(mb0, 1);
        mbar_init(mb1, 1);
        mbar_expect_tx(mb0, 512);
        mbar_expect_tx(mb1, 512);
    }
    if (t < 128) hS[0][t] = 0.0f;     // h0 = 0 (zero in any layout)
    __syncthreads();
    asm volatile("barrier.cluster.arrive.aligned;" ::: "memory");
    asm volatile("barrier.cluster.wait.aligned;" ::: "memory");

    const uint32_t prB0 = mapa_u32(smem_u32(&pbuf[0][0]), rank ^ 1);
    const uint32_t prB1 = mapa_u32(smem_u32(&pbuf[1][0]), rank ^ 1);
    const uint32_t pmb0 = mapa_u32(mb0, rank ^ 1);
    const uint32_t pmb1 = mapa_u32(mb1, rank ^ 1);

    // every kc0 lane ships its own P as f32 (128 x 4B = 512B)
    const bool shipper = (kc == 0);
    const uint32_t shipoff = (uint32_t)jl * 4u;

    // wait for xw chunk 0 (t0 spins, block follows)
    {
        if (t == 0) {
            volatile int* f = &g_flags[row][0];
            while (*f < 2) __nanosleep(512);
        }
        __syncthreads();
        __threadfence();
    }

    float* xwp = out + (long)row * S_LEN * H_DIM + jg;
    float xw_next = xwp[0];

    for (int step = 0; step < S_LEN; step++) {
        const int b = step & 1;
        float xw_cur = xw_next;
        if (step + 1 < S_LEN) {
            if (((step + 1) & (CHUNK - 1)) == 0) {      // entering a new chunk
                if (t == 0) {
                    volatile int* f = &g_flags[row][(step + 1) >> 7];
                    while (*f < 2) __nanosleep(512);
                }
                __syncthreads();
                __threadfence();
            }
            xw_next = xwp[(long)(step + 1) * H_DIM];
        }

        // ---- merged P+L FMA loop: each h chunk loaded ONCE (16 LDS.128) ----
        const float* hb = &hS[b][0];
        unsigned long long pA = 0ull, pB = 0ull, lA = 0ull, lB = 0ull;
#pragma unroll
        for (int u = 0; u < 16; u++) {
            ulonglong2 hv = *(const ulonglong2*)(hb + u * 8 + kc * 4);
            pA = ffma2(hv.x, wPA[u], pA);
            pB = ffma2(hv.y, wPB[u], pB);
            lA = ffma2(hv.x, wLA[u], lA);
            lB = ffma2(hv.y, wLB[u], lB);
        }

        float2 gp0 = unpack2(pA), gp1 = unpack2(pB);
        float P = (gp0.x + gp0.y) + (gp1.x + gp1.y);
        P += __shfl_xor_sync(0xffffffffu, P, 1);        // sum over kc

        if (shipper)
            st_async_f32((b ? prB1 : prB0) + shipoff, P, b ? pmb1 : pmb0);

        float2 gl0 = unpack2(lA), gl1 = unpack2(lB);
        float L = (gl0.x + gl0.y) + (gl1.x + gl1.y);
        L += __shfl_xor_sync(0xffffffffu, L, 1);
        const float base = L + xw_cur;                   // ready before wait

        // ---- wait for peer's partials, finish the step ----
        mbar_wait(b ? mb1 : mb0, (step >> 1) & 1);
        if (t == 3) mbar_expect_tx(b ? mb1 : mb0, 512);  // re-arm for step+2

        float v = tanh_fast(base + pbuf[b][jl]);

        if (kc == 0) {
            hS[b ^ 1][hpos] = v;                         // interleaved store
        } else {
            xwp[(long)step * H_DIM] = v;                 // in-place output
            if (step == S_LEN - 1)
                out[(long)B_DIM * S_LEN * H_DIM + (long)row * H_DIM + jg] = v;
        }

        __syncthreads();
    }

    asm volatile("barrier.cluster.arrive.aligned;" ::: "memory");
    asm volatile("barrier.cluster.wait.aligned;" ::: "memory");
}

// ---------------------------------------------------------------------------
// Launch
// ---------------------------------------------------------------------------
extern "C" void kernel_launch(void* const* d_in, const int* in_sizes, int n_in,
                              void* d_out, int out_size) {
    const float* x    = (const float*)d_in[0];  // [B,S,I]
    const float* Wx_w = (const float*)d_in[1];  // [H,I]
    const float* Wx_b = (const float*)d_in[2];  // [H]
    const float* Wh_w = (const float*)d_in[3];  // [H,H]
    float* out = (float*)d_out;                 // [B,S,H] ++ [B,H]

    flag_init_kernel<<<1, 512>>>();

    dim3 g(2, REC_Y + GEMM_MT);                 // (2, 544)
    srnn_fused_kernel<<<g, 256>>>(x, Wx_w, Wx_b, Wh_w, out);
}